// round 2
// baseline (speedup 1.0000x reference)
#include <cuda_runtime.h>
#include <cuda_bf16.h>
#include <cstdint>
#include <cmath>

// ---------------- problem constants ----------------
#define BS      4096        // B*S
#define HDIM    2048        // hidden
#define KD      256         // KDIM
#define KN      1024        // key_num
#define HEADS   2
#define RANK    2
#define KNN     32
#define VE      4           // VALUE_EXPAND
#define VD      256         // vdim
#define VN      262144      // value_num (2^18)
#define SCOL    (HEADS*KN*RANK)   // 4096 columns of the score GEMM

// ---------------- device scratch (static device globals; no allocations) ------
__device__ float g_qraw[BS * 2 * KD];          // 8 MB
__device__ float g_qn0 [BS * KD];              // 4 MB
__device__ float g_qn1 [BS * KD];              // 4 MB
__device__ float g_kb0 [KD * SCOL];            // 4 MB (side 0, d-major rows)
__device__ float g_kb1 [KD * SCOL];            // 4 MB
__device__ float g_sr0 [(size_t)BS * SCOL];    // 64 MB
__device__ float g_sr1 [(size_t)BS * SCOL];    // 64 MB
__device__ float g_wsel[BS * HEADS * KNN];
__device__ int   g_vsel[BS * HEADS * KNN];
__device__ int   g_esel[BS * HEADS * KNN];
__device__ float g_agg [BS * VE * VD];         // 16 MB

// Scratch-buffer tags: resolved in DEVICE code, so the host launch path has
// zero runtime-API calls (fully graph-capture-clean).
#define TAG_EXT  (-1)
#define TAG_QRAW 0
#define TAG_QN0  1
#define TAG_QN1  2
#define TAG_KB0  3
#define TAG_KB1  4
#define TAG_SR0  5
#define TAG_SR1  6
#define TAG_AGG  7

__device__ __forceinline__ float* scratch_ptr(int tag) {
    switch (tag) {
        case TAG_QRAW: return g_qraw;
        case TAG_QN0:  return g_qn0;
        case TAG_QN1:  return g_qn1;
        case TAG_KB0:  return g_kb0;
        case TAG_KB1:  return g_kb1;
        case TAG_SR0:  return g_sr0;
        case TAG_SR1:  return g_sr1;
        case TAG_AGG:  return g_agg;
    }
    return nullptr;
}

// ---------------- SGEMM: C(MxN) = A(MxK) * B(KxN), all row-major ----------------
// BM=BN=128, BK=16, 256 threads, 8x8 per thread. M%128==0, N%128==0, K%16==0.
template<int TA, int TB, int TC>
__global__ __launch_bounds__(256) void sgemm_kernel(
    const float* __restrict__ Aext, const float* __restrict__ Bext,
    float* __restrict__ Cext, int M, int N, int K)
{
    const float* A = (TA == TAG_EXT) ? Aext : scratch_ptr(TA);
    const float* B = (TB == TAG_EXT) ? Bext : scratch_ptr(TB);
    float*       C = (TC == TAG_EXT) ? Cext : scratch_ptr(TC);

    __shared__ __align__(16) float As[16][128];
    __shared__ __align__(16) float Bs[16][128];

    const int tid = threadIdx.x;
    const int bx  = blockIdx.x;   // N tile
    const int by  = blockIdx.y;   // M tile
    const int tx  = tid & 15;     // 0..15
    const int ty  = tid >> 4;     // 0..15

    const int ARow  = tid >> 2;          // 0..63
    const int ACol4 = (tid & 3) << 2;    // 0,4,8,12
    const int BRow  = tid >> 5;          // 0..7
    const int BCol4 = (tid & 31) << 2;   // 0..124

    float acc[8][8];
    #pragma unroll
    for (int i = 0; i < 8; i++)
        #pragma unroll
        for (int j = 0; j < 8; j++) acc[i][j] = 0.f;

    const float* Ab = A + (size_t)(by * 128) * K;
    const float* Bb = B + bx * 128;

    for (int k0 = 0; k0 < K; k0 += 16) {
        #pragma unroll
        for (int i = 0; i < 128; i += 64) {
            float4 v = *(const float4*)&Ab[(size_t)(ARow + i) * K + k0 + ACol4];
            As[ACol4 + 0][ARow + i] = v.x;
            As[ACol4 + 1][ARow + i] = v.y;
            As[ACol4 + 2][ARow + i] = v.z;
            As[ACol4 + 3][ARow + i] = v.w;
        }
        #pragma unroll
        for (int i = 0; i < 16; i += 8) {
            float4 v = *(const float4*)&Bb[(size_t)(k0 + BRow + i) * N + BCol4];
            *(float4*)&Bs[BRow + i][BCol4] = v;
        }
        __syncthreads();

        #pragma unroll
        for (int kk = 0; kk < 16; kk++) {
            float4 a0 = *(const float4*)&As[kk][ty * 8];
            float4 a1 = *(const float4*)&As[kk][ty * 8 + 4];
            float4 b0 = *(const float4*)&Bs[kk][tx * 8];
            float4 b1 = *(const float4*)&Bs[kk][tx * 8 + 4];
            float ar[8] = {a0.x,a0.y,a0.z,a0.w,a1.x,a1.y,a1.z,a1.w};
            float br[8] = {b0.x,b0.y,b0.z,b0.w,b1.x,b1.y,b1.z,b1.w};
            #pragma unroll
            for (int i = 0; i < 8; i++)
                #pragma unroll
                for (int j = 0; j < 8; j++) acc[i][j] += ar[i] * br[j];
        }
        __syncthreads();
    }

    float* Cb = C + (size_t)(by * 128 + ty * 8) * N + bx * 128 + tx * 8;
    #pragma unroll
    for (int i = 0; i < 8; i++) {
        *(float4*)&Cb[(size_t)i * N + 0] = make_float4(acc[i][0], acc[i][1], acc[i][2], acc[i][3]);
        *(float4*)&Cb[(size_t)i * N + 4] = make_float4(acc[i][4], acc[i][5], acc[i][6], acc[i][7]);
    }
}

// ---------------- q layernorm: per (b, side) row of 256 ----------------
__global__ __launch_bounds__(256) void qln_kernel(const float* __restrict__ w)
{
    const int row  = blockIdx.x;          // 0..8191 : b*2 + side
    const int b    = row >> 1;
    const int side = row & 1;
    const int tid  = threadIdx.x;

    float x = g_qraw[(size_t)row * 256 + tid];
    float s = x, q = x * x;
    #pragma unroll
    for (int off = 16; off; off >>= 1) {
        s += __shfl_xor_sync(0xffffffffu, s, off);
        q += __shfl_xor_sync(0xffffffffu, q, off);
    }
    __shared__ float ss[8], sq[8];
    if ((tid & 31) == 0) { ss[tid >> 5] = s; sq[tid >> 5] = q; }
    __syncthreads();
    if (tid < 32) {
        s = (tid < 8) ? ss[tid] : 0.f;
        q = (tid < 8) ? sq[tid] : 0.f;
        #pragma unroll
        for (int off = 4; off; off >>= 1) {
            s += __shfl_xor_sync(0xffffffffu, s, off);
            q += __shfl_xor_sync(0xffffffffu, q, off);
        }
        if (tid == 0) { ss[0] = s; sq[0] = q; }
    }
    __syncthreads();
    float mean = ss[0] * (1.f / 256.f);
    float var  = sq[0] * (1.f / 256.f) - mean * mean;
    float rs   = rsqrtf(var + 1e-5f);
    float outv = (x - mean) * rs * w[tid];
    (side ? g_qn1 : g_qn0)[(size_t)b * 256 + tid] = outv;
}

// ---------------- keys normalization -> d-major B matrix for the score GEMM ----
// block = one (h, side, k); thread = d. Normalization over d per rank.
__global__ __launch_bounds__(256) void keysn_kernel(
    const float* __restrict__ keys, const float* __restrict__ knw)
{
    const int bi   = blockIdx.x;          // 0..4095
    const int h    = bi >> 11;
    const int side = (bi >> 10) & 1;
    const int k    = bi & 1023;
    const int tid  = threadIdx.x;         // = d

    const size_t base = ((((size_t)h * 2 + side) * KN + k) * KD + tid) * RANK;
    float x0 = keys[base + 0];
    float x1 = keys[base + 1];
    float s0 = x0, s1 = x1, q0 = x0 * x0, q1 = x1 * x1;
    #pragma unroll
    for (int off = 16; off; off >>= 1) {
        s0 += __shfl_xor_sync(0xffffffffu, s0, off);
        s1 += __shfl_xor_sync(0xffffffffu, s1, off);
        q0 += __shfl_xor_sync(0xffffffffu, q0, off);
        q1 += __shfl_xor_sync(0xffffffffu, q1, off);
    }
    __shared__ float sm[4][8];
    if ((tid & 31) == 0) {
        int w = tid >> 5;
        sm[0][w] = s0; sm[1][w] = s1; sm[2][w] = q0; sm[3][w] = q1;
    }
    __syncthreads();
    if (tid < 32) {
        s0 = (tid < 8) ? sm[0][tid] : 0.f;
        s1 = (tid < 8) ? sm[1][tid] : 0.f;
        q0 = (tid < 8) ? sm[2][tid] : 0.f;
        q1 = (tid < 8) ? sm[3][tid] : 0.f;
        #pragma unroll
        for (int off = 4; off; off >>= 1) {
            s0 += __shfl_xor_sync(0xffffffffu, s0, off);
            s1 += __shfl_xor_sync(0xffffffffu, s1, off);
            q0 += __shfl_xor_sync(0xffffffffu, q0, off);
            q1 += __shfl_xor_sync(0xffffffffu, q1, off);
        }
        if (tid == 0) { sm[0][0] = s0; sm[1][0] = s1; sm[2][0] = q0; sm[3][0] = q1; }
    }
    __syncthreads();
    float m0 = sm[0][0] * (1.f / 256.f), m1 = sm[1][0] * (1.f / 256.f);
    float v0 = sm[2][0] * (1.f / 256.f) - m0 * m0;
    float v1 = sm[3][0] * (1.f / 256.f) - m1 * m1;
    float r0 = rsqrtf(v0 + 1e-5f), r1 = rsqrtf(v1 + 1e-5f);
    float kw = knw[tid];
    float n0 = (x0 - m0) * r0 * kw;
    float n1 = (x1 - m1) * r1 * kw;

    float* kb = side ? g_kb1 : g_kb0;
    const int col = (h * KN + k) * RANK;
    kb[(size_t)tid * SCOL + col + 0] = n0;
    kb[(size_t)tid * SCOL + col + 1] = n1;
}

// ---------------- block argmax (lowest index on ties, matching jax top_k) ------
__device__ __forceinline__ void argmax_block(
    const float* s, int n, float* redv, int* redi, float& outVal, int& outIdx)
{
    const int tid = threadIdx.x;
    float bv = -INFINITY; int bi = 0x7fffffff;
    for (int k = tid; k < n; k += 256) {
        float v = s[k];
        if (v > bv || (v == bv && k < bi)) { bv = v; bi = k; }
    }
    #pragma unroll
    for (int off = 16; off; off >>= 1) {
        float ov = __shfl_down_sync(0xffffffffu, bv, off);
        int   oi = __shfl_down_sync(0xffffffffu, bi, off);
        if (ov > bv || (ov == bv && oi < bi)) { bv = ov; bi = oi; }
    }
    if ((tid & 31) == 0) { redv[tid >> 5] = bv; redi[tid >> 5] = bi; }
    __syncthreads();
    if (tid < 32) {
        bv = (tid < 8) ? redv[tid] : -INFINITY;
        bi = (tid < 8) ? redi[tid] : 0x7fffffff;
        #pragma unroll
        for (int off = 4; off; off >>= 1) {
            float ov = __shfl_down_sync(0xffffffffu, bv, off);
            int   oi = __shfl_down_sync(0xffffffffu, bi, off);
            if (ov > bv || (ov == bv && oi < bi)) { bv = ov; bi = oi; }
        }
        if (tid == 0) { redv[0] = bv; redi[0] = bi; }
    }
    __syncthreads();
    outVal = redv[0]; outIdx = redi[0];
}

// ---------------- selection: per (b,h) topk + cross topk + softmax ------------
__global__ __launch_bounds__(256) void select_kernel(
    const float* __restrict__ core, const float* __restrict__ tu,
    const float* __restrict__ tv, const int* __restrict__ shuf)
{
    const int b = blockIdx.x;
    const int h = blockIdx.y;
    const int tid = threadIdx.x;

    __shared__ float s[1024];
    __shared__ float g1[32][2], g2[32][2];
    __shared__ int   i1[32], i2[32];
    __shared__ float redv[8]; __shared__ int redi[8];
    __shared__ float ssel[32]; __shared__ int vsel[32]; __shared__ int esel[32];

    const float* row0 = g_sr0 + (size_t)b * SCOL + h * (KN * RANK);
    const float* row1 = g_sr1 + (size_t)b * SCOL + h * (KN * RANK);
    const float u0 = tu[h * 2 + 0], u1 = tu[h * 2 + 1];
    const float v0 = tv[h * 2 + 0], v1 = tv[h * 2 + 1];

    // ---- side 1 top-32 ----
    for (int k = tid; k < 1024; k += 256) s[k] = row0[2 * k] * u0 + row0[2 * k + 1] * u1;
    __syncthreads();
    for (int t = 0; t < 32; t++) {
        int idx; float val;
        argmax_block(s, 1024, redv, redi, val, idx);
        if (tid == 0) {
            i1[t] = idx; g1[t][0] = row0[2 * idx]; g1[t][1] = row0[2 * idx + 1];
            s[idx] = -INFINITY;
        }
        __syncthreads();
    }

    // ---- side 2 top-32 ----
    for (int k = tid; k < 1024; k += 256) s[k] = row1[2 * k] * v0 + row1[2 * k + 1] * v1;
    __syncthreads();
    for (int t = 0; t < 32; t++) {
        int idx; float val;
        argmax_block(s, 1024, redv, redi, val, idx);
        if (tid == 0) {
            i2[t] = idx; g2[t][0] = row1[2 * idx]; g2[t][1] = row1[2 * idx + 1];
            s[idx] = -INFINITY;
        }
        __syncthreads();
    }

    // ---- cross scores: coreh = sum_m core[m,h] (einsum sums over m) ----
    const float c00 = core[(0*2 + h)*4 + 0] + core[(1*2 + h)*4 + 0];
    const float c01 = core[(0*2 + h)*4 + 1] + core[(1*2 + h)*4 + 1];
    const float c10 = core[(0*2 + h)*4 + 2] + core[(1*2 + h)*4 + 2];
    const float c11 = core[(0*2 + h)*4 + 3] + core[(1*2 + h)*4 + 3];
    for (int idx = tid; idx < 1024; idx += 256) {
        int k = idx >> 5, l = idx & 31;
        float a = g1[k][0] * (c00 * g2[l][0] + c01 * g2[l][1])
                + g1[k][1] * (c10 * g2[l][0] + c11 * g2[l][1]);
        s[idx] = a;
    }
    __syncthreads();

    // ---- cross top-32 + index decode ----
    for (int t = 0; t < 32; t++) {
        int idx; float val;
        argmax_block(s, 1024, redv, redi, val, idx);
        if (tid == 0) {
            int k = idx >> 5, l = idx & 31;
            int bi2 = i1[k] * KN + i2[l];        // < 2^20
            int sh  = shuf[bi2];
            ssel[t] = val;
            vsel[t] = sh & (VN - 1);
            esel[t] = sh >> 18;
            s[idx]  = -INFINITY;
        }
        __syncthreads();
    }

    // ---- softmax over the 32 best (ssel[0] is the max) ----
    if (tid < 32) {
        float m = ssel[0];
        float e = expf(ssel[tid] - m);
        float sum = e;
        #pragma unroll
        for (int off = 16; off; off >>= 1) sum += __shfl_xor_sync(0xffffffffu, sum, off);
        const int base = (b * 2 + h) * 32 + tid;
        g_wsel[base] = e / sum;
        g_vsel[base] = vsel[tid];
        g_esel[base] = esel[tid];
    }
}

// ---------------- value gather + aggregate into agg[b][1024] ------------------
__global__ __launch_bounds__(256) void agg_kernel(const float* __restrict__ values)
{
    const int b = blockIdx.x;
    const int tid = threadIdx.x;
    __shared__ float acc[VE * VD];
    #pragma unroll
    for (int i = 0; i < 4; i++) acc[i * 256 + tid] = 0.f;
    __syncthreads();
    #pragma unroll 4
    for (int j = 0; j < 64; j++) {
        const int base = b * 64 + j;
        float w = g_wsel[base];
        int vi = g_vsel[base];
        int ei = g_esel[base];
        acc[ei * 256 + tid] += w * values[(size_t)vi * 256 + tid];
    }
    __syncthreads();
    #pragma unroll
    for (int i = 0; i < 4; i++)
        g_agg[(size_t)b * 1024 + i * 256 + tid] = acc[i * 256 + tid];
}

// ---------------- launch (kernel launches ONLY — no runtime API calls) --------
extern "C" void kernel_launch(void* const* d_in, const int* in_sizes, int n_in,
                              void* d_out, int out_size)
{
    const float* hidden = (const float*)d_in[0];
    const float* wq     = (const float*)d_in[1];
    const float* qnw    = (const float*)d_in[2];
    const float* knw    = (const float*)d_in[3];
    const float* keys   = (const float*)d_in[4];
    const float* core   = (const float*)d_in[5];
    const float* tu     = (const float*)d_in[6];
    const float* tv     = (const float*)d_in[7];
    const float* values = (const float*)d_in[8];
    const float* wvm    = (const float*)d_in[9];
    const int*   shuf   = (const int*)d_in[10];
    float* out = (float*)d_out;

    // 1) q = hidden @ wq : (4096x2048)@(2048x512) -> g_qraw
    sgemm_kernel<TAG_EXT, TAG_EXT, TAG_QRAW>
        <<<dim3(512/128, BS/128), 256>>>(hidden, wq, nullptr, BS, 512, HDIM);
    // 2) layernorm q -> g_qn0/g_qn1
    qln_kernel<<<BS * 2, 256>>>(qnw);
    // 3) normalize keys -> d-major score-B matrices g_kb0/g_kb1
    keysn_kernel<<<HEADS * 2 * KN, 256>>>(keys, knw);
    // 4) score GEMMs: (4096x256)@(256x4096) per side -> g_sr0/g_sr1
    sgemm_kernel<TAG_QN0, TAG_KB0, TAG_SR0>
        <<<dim3(SCOL/128, BS/128), 256>>>(nullptr, nullptr, nullptr, BS, SCOL, KD);
    sgemm_kernel<TAG_QN1, TAG_KB1, TAG_SR1>
        <<<dim3(SCOL/128, BS/128), 256>>>(nullptr, nullptr, nullptr, BS, SCOL, KD);
    // 5) topk / cross-scores / topk / softmax -> g_wsel/g_vsel/g_esel
    select_kernel<<<dim3(BS, HEADS), 256>>>(core, tu, tv, shuf);
    // 6) gather values, aggregate -> g_agg[b][1024]
    agg_kernel<<<BS, 256>>>(values);
    // 7) out = agg @ wv : (4096x1024)@(1024x2048) -> d_out
    sgemm_kernel<TAG_AGG, TAG_EXT, TAG_EXT>
        <<<dim3(HDIM/128, BS/128), 256>>>(nullptr, wvm, out, BS, HDIM, 1024);
}

// round 12
// speedup vs baseline: 1.5207x; 1.5207x over previous
#include <cuda_runtime.h>
#include <cuda_bf16.h>
#include <cstdint>
#include <cmath>

#define BS      4096
#define HDIM    2048
#define KD      256
#define KN      1024
#define VE      4
#define VD      256
#define VN      262144
#define SCOL    4096

// ---------------- device scratch (static; no allocations anywhere) ------------
// fp32 (R2-proven pre-selection path)
__device__ float g_qraw[(size_t)BS * 512];
__device__ float g_qn0 [(size_t)BS * KD];
__device__ float g_qn1 [(size_t)BS * KD];
__device__ float g_kb0 [(size_t)KD * SCOL];
__device__ float g_kb1 [(size_t)KD * SCOL];
__device__ float g_sr0 [(size_t)BS * SCOL];
__device__ float g_sr1 [(size_t)BS * SCOL];
__device__ float g_wsel[BS * 64];
__device__ int   g_vsel[BS * 64];
__device__ int   g_esel[BS * 64];
// bf16 3-term split operands for the post-selection out-GEMM (validated R6<->R11)
__device__ __nv_bfloat16 g_agg3[(size_t)BS   * 3072];  // A {h,h,m}
__device__ __nv_bfloat16 g_wvt3[(size_t)HDIM * 3072];  // B {h,m,h}

enum { TAGF_EXT = -1, TAGF_QRAW, TAGF_QN0, TAGF_QN1, TAGF_KB0, TAGF_KB1,
       TAGF_SR0, TAGF_SR1 };

__device__ __forceinline__ float* scratch_f32(int tag) {
    switch (tag) {
        case TAGF_QRAW: return g_qraw;
        case TAGF_QN0:  return g_qn0;
        case TAGF_QN1:  return g_qn1;
        case TAGF_KB0:  return g_kb0;
        case TAGF_KB1:  return g_kb1;
        case TAGF_SR0:  return g_sr0;
        case TAGF_SR1:  return g_sr1;
    }
    return nullptr;
}

// ---------------- PTX helpers (sm_100 base target only) ----------------
__device__ __forceinline__ uint32_t smem_u32(const void* p) {
    uint32_t a;
    asm("{ .reg .u64 t; cvta.to.shared.u64 t, %1; cvt.u32.u64 %0, t; }" : "=r"(a) : "l"(p));
    return a;
}
__device__ __forceinline__ void cpasync16(uint32_t saddr, const void* g) {
    asm volatile("cp.async.cg.shared.global [%0], [%1], 16;" :: "r"(saddr), "l"(g));
}
#define CP_COMMIT() asm volatile("cp.async.commit_group;" ::: "memory")
#define LDSM4(r0, r1, r2, r3, addr)                                           \
    asm volatile("ldmatrix.sync.aligned.m8n8.x4.shared.b16 {%0,%1,%2,%3}, [%4];" \
                 : "=r"(r0), "=r"(r1), "=r"(r2), "=r"(r3) : "r"(addr))
#define MMA16816(d, a0, a1, a2, a3, b0, b1)                                   \
    asm volatile("mma.sync.aligned.m16n8k16.row.col.f32.bf16.bf16.f32 "       \
                 "{%0,%1,%2,%3}, {%4,%5,%6,%7}, {%8,%9}, {%0,%1,%2,%3};"      \
                 : "+f"((d)[0]), "+f"((d)[1]), "+f"((d)[2]), "+f"((d)[3])     \
                 : "r"(a0), "r"(a1), "r"(a2), "r"(a3), "r"(b0), "r"(b1))

__device__ __forceinline__ void split3(float x, __nv_bfloat16& h,
                                       __nv_bfloat16& m, __nv_bfloat16& l) {
    h = __float2bfloat16(x);
    float r = x - __bfloat162float(h);
    m = __float2bfloat16(r);
    l = __float2bfloat16(r - __bfloat162float(m));
}

// ---------------- R2-proven fp32 SGEMM: C = A(MxK) * B(KxN), row-major --------
template<int TA, int TB, int TC>
__global__ __launch_bounds__(256) void sgemm_kernel(
    const float* __restrict__ Aext, const float* __restrict__ Bext,
    float* __restrict__ Cext, int M, int N, int K)
{
    const float* A = (TA == TAGF_EXT) ? Aext : scratch_f32(TA);
    const float* B = (TB == TAGF_EXT) ? Bext : scratch_f32(TB);
    float*       C = (TC == TAGF_EXT) ? Cext : scratch_f32(TC);

    __shared__ __align__(16) float As[16][128];
    __shared__ __align__(16) float Bs[16][128];

    const int tid = threadIdx.x;
    const int bx  = blockIdx.x;
    const int by  = blockIdx.y;
    const int tx  = tid & 15;
    const int ty  = tid >> 4;

    const int ARow  = tid >> 2;
    const int ACol4 = (tid & 3) << 2;
    const int BRow  = tid >> 5;
    const int BCol4 = (tid & 31) << 2;

    float acc[8][8];
    #pragma unroll
    for (int i = 0; i < 8; i++)
        #pragma unroll
        for (int j = 0; j < 8; j++) acc[i][j] = 0.f;

    const float* Ab = A + (size_t)(by * 128) * K;
    const float* Bb = B + bx * 128;

    for (int k0 = 0; k0 < K; k0 += 16) {
        #pragma unroll
        for (int i = 0; i < 128; i += 64) {
            float4 v = *(const float4*)&Ab[(size_t)(ARow + i) * K + k0 + ACol4];
            As[ACol4 + 0][ARow + i] = v.x;
            As[ACol4 + 1][ARow + i] = v.y;
            As[ACol4 + 2][ARow + i] = v.z;
            As[ACol4 + 3][ARow + i] = v.w;
        }
        #pragma unroll
        for (int i = 0; i < 16; i += 8) {
            float4 v = *(const float4*)&Bb[(size_t)(k0 + BRow + i) * N + BCol4];
            *(float4*)&Bs[BRow + i][BCol4] = v;
        }
        __syncthreads();

        #pragma unroll
        for (int kk = 0; kk < 16; kk++) {
            float4 a0 = *(const float4*)&As[kk][ty * 8];
            float4 a1 = *(const float4*)&As[kk][ty * 8 + 4];
            float4 b0 = *(const float4*)&Bs[kk][tx * 8];
            float4 b1 = *(const float4*)&Bs[kk][tx * 8 + 4];
            float ar[8] = {a0.x,a0.y,a0.z,a0.w,a1.x,a1.y,a1.z,a1.w};
            float br[8] = {b0.x,b0.y,b0.z,b0.w,b1.x,b1.y,b1.z,b1.w};
            #pragma unroll
            for (int i = 0; i < 8; i++)
                #pragma unroll
                for (int j = 0; j < 8; j++) acc[i][j] += ar[i] * br[j];
        }
        __syncthreads();
    }

    float* Cb = C + (size_t)(by * 128 + ty * 8) * N + bx * 128 + tx * 8;
    #pragma unroll
    for (int i = 0; i < 8; i++) {
        *(float4*)&Cb[(size_t)i * N + 0] = make_float4(acc[i][0], acc[i][1], acc[i][2], acc[i][3]);
        *(float4*)&Cb[(size_t)i * N + 4] = make_float4(acc[i][4], acc[i][5], acc[i][6], acc[i][7]);
    }
}

// ---------------- R2-proven q layernorm (fp32 out) ----------------
__global__ __launch_bounds__(256) void qln_kernel(const float* __restrict__ w)
{
    const int row  = blockIdx.x;
    const int b    = row >> 1;
    const int side = row & 1;
    const int tid  = threadIdx.x;

    float x = g_qraw[(size_t)row * 256 + tid];
    float s = x, q = x * x;
    #pragma unroll
    for (int off = 16; off; off >>= 1) {
        s += __shfl_xor_sync(0xffffffffu, s, off);
        q += __shfl_xor_sync(0xffffffffu, q, off);
    }
    __shared__ float ss[8], sq[8];
    if ((tid & 31) == 0) { ss[tid >> 5] = s; sq[tid >> 5] = q; }
    __syncthreads();
    if (tid < 32) {
        s = (tid < 8) ? ss[tid] : 0.f;
        q = (tid < 8) ? sq[tid] : 0.f;
        #pragma unroll
        for (int off = 4; off; off >>= 1) {
            s += __shfl_xor_sync(0xffffffffu, s, off);
            q += __shfl_xor_sync(0xffffffffu, q, off);
        }
        if (tid == 0) { ss[0] = s; sq[0] = q; }
    }
    __syncthreads();
    float mean = ss[0] * (1.f / 256.f);
    float var  = sq[0] * (1.f / 256.f) - mean * mean;
    float rs   = rsqrtf(var + 1e-5f);
    float outv = (x - mean) * rs * w[tid];
    (side ? g_qn1 : g_qn0)[(size_t)b * 256 + tid] = outv;
}

// ---------------- R2-proven keys normalization -> d-major fp32 kb --------------
__global__ __launch_bounds__(256) void keysn_kernel(
    const float* __restrict__ keys, const float* __restrict__ knw)
{
    const int bi   = blockIdx.x;
    const int h    = bi >> 11;
    const int side = (bi >> 10) & 1;
    const int k    = bi & 1023;
    const int tid  = threadIdx.x;

    const size_t base = ((((size_t)h * 2 + side) * KN + k) * KD + tid) * 2;
    float x0 = keys[base + 0];
    float x1 = keys[base + 1];
    float s0 = x0, s1 = x1, q0 = x0 * x0, q1 = x1 * x1;
    #pragma unroll
    for (int off = 16; off; off >>= 1) {
        s0 += __shfl_xor_sync(0xffffffffu, s0, off);
        s1 += __shfl_xor_sync(0xffffffffu, s1, off);
        q0 += __shfl_xor_sync(0xffffffffu, q0, off);
        q1 += __shfl_xor_sync(0xffffffffu, q1, off);
    }
    __shared__ float sm[4][8];
    if ((tid & 31) == 0) {
        int w = tid >> 5;
        sm[0][w] = s0; sm[1][w] = s1; sm[2][w] = q0; sm[3][w] = q1;
    }
    __syncthreads();
    if (tid < 32) {
        s0 = (tid < 8) ? sm[0][tid] : 0.f;
        s1 = (tid < 8) ? sm[1][tid] : 0.f;
        q0 = (tid < 8) ? sm[2][tid] : 0.f;
        q1 = (tid < 8) ? sm[3][tid] : 0.f;
        #pragma unroll
        for (int off = 4; off; off >>= 1) {
            s0 += __shfl_xor_sync(0xffffffffu, s0, off);
            s1 += __shfl_xor_sync(0xffffffffu, s1, off);
            q0 += __shfl_xor_sync(0xffffffffu, q0, off);
            q1 += __shfl_xor_sync(0xffffffffu, q1, off);
        }
        if (tid == 0) { sm[0][0] = s0; sm[1][0] = s1; sm[2][0] = q0; sm[3][0] = q1; }
    }
    __syncthreads();
    float m0 = sm[0][0] * (1.f / 256.f), m1 = sm[1][0] * (1.f / 256.f);
    float v0 = sm[2][0] * (1.f / 256.f) - m0 * m0;
    float v1 = sm[3][0] * (1.f / 256.f) - m1 * m1;
    float r0 = rsqrtf(v0 + 1e-5f), r1 = rsqrtf(v1 + 1e-5f);
    float kw = knw[tid];
    float n0 = (x0 - m0) * r0 * kw;
    float n1 = (x1 - m1) * r1 * kw;

    float* kb = side ? g_kb1 : g_kb0;
    const int col = (h * KN + k) * 2;
    kb[(size_t)tid * SCOL + col + 0] = n0;
    kb[(size_t)tid * SCOL + col + 1] = n1;
}

// ---------------- warp-parallel exact top-32 (validated ≡ serial, R6 vs R11) --
__device__ __forceinline__ void warp_extract_top32(float* s, float* outv, int* outi)
{
    const int lane = threadIdx.x & 31;
    float mv = -INFINITY; int mi = lane;
    #pragma unroll 4
    for (int j = 0; j < 32; j++) {
        float v = s[j * 32 + lane];
        if (v > mv) { mv = v; mi = j * 32 + lane; }
    }
    for (int t = 0; t < 32; t++) {
        float bv = mv; int bi = mi;
        #pragma unroll
        for (int o = 16; o; o >>= 1) {
            float ov = __shfl_down_sync(0xffffffffu, bv, o);
            int   oi = __shfl_down_sync(0xffffffffu, bi, o);
            if (ov > bv || (ov == bv && oi < bi)) { bv = ov; bi = oi; }
        }
        bv = __shfl_sync(0xffffffffu, bv, 0);
        bi = __shfl_sync(0xffffffffu, bi, 0);
        if (lane == 0) { outv[t] = bv; outi[t] = bi; }
        if ((bi & 31) == lane) {
            s[bi] = -INFINITY;
            mv = -INFINITY; mi = lane;
            #pragma unroll 4
            for (int j = 0; j < 32; j++) {
                float v = s[j * 32 + lane];
                if (v > mv) { mv = v; mi = j * 32 + lane; }
            }
        }
    }
}

// ---------------- selection (warp-parallel; validated) ----------------
__global__ __launch_bounds__(256) void select_kernel(
    const float* __restrict__ core, const float* __restrict__ tu,
    const float* __restrict__ tv, const int* __restrict__ shuf)
{
    const int b = blockIdx.x, h = blockIdx.y, tid = threadIdx.x, wid = tid >> 5;
    __shared__ float s1[1024], s2[1024], cs[1024];
    __shared__ float g1v[32][2], g2v[32][2];
    __shared__ int   i1[32], i2[32], ci[32];
    __shared__ float sv1[32], sv2[32], ssel[32];

    const float* row0 = g_sr0 + (size_t)b * SCOL + h * 2048;
    const float* row1 = g_sr1 + (size_t)b * SCOL + h * 2048;
    const float u0 = tu[h*2], u1 = tu[h*2+1], v0 = tv[h*2], v1 = tv[h*2+1];

    for (int k = tid; k < 1024; k += 256) {
        s1[k] = row0[2*k] * u0 + row0[2*k+1] * u1;
        s2[k] = row1[2*k] * v0 + row1[2*k+1] * v1;
    }
    __syncthreads();
    if (wid == 0) warp_extract_top32(s1, sv1, i1);
    if (wid == 1) warp_extract_top32(s2, sv2, i2);
    __syncthreads();
    if (tid < 32)      { int x = i1[tid];  g1v[tid][0]=row0[2*x]; g1v[tid][1]=row0[2*x+1]; }
    else if (tid < 64) { int t = tid - 32; int x = i2[t];
                         g2v[t][0]=row1[2*x]; g2v[t][1]=row1[2*x+1]; }
    __syncthreads();

    const float c00 = core[(0*2+h)*4+0] + core[(1*2+h)*4+0];
    const float c01 = core[(0*2+h)*4+1] + core[(1*2+h)*4+1];
    const float c10 = core[(0*2+h)*4+2] + core[(1*2+h)*4+2];
    const float c11 = core[(0*2+h)*4+3] + core[(1*2+h)*4+3];
    for (int idx = tid; idx < 1024; idx += 256) {
        int k = idx >> 5, l = idx & 31;
        cs[idx] = g1v[k][0] * (c00 * g2v[l][0] + c01 * g2v[l][1])
                + g1v[k][1] * (c10 * g2v[l][0] + c11 * g2v[l][1]);
    }
    __syncthreads();
    if (wid == 0) warp_extract_top32(cs, ssel, ci);
    __syncthreads();

    if (tid < 32) {
        int idx = ci[tid], k = idx >> 5, l = idx & 31;
        int sh = shuf[i1[k] * KN + i2[l]];
        float mx = ssel[0];
        float e = expf(ssel[tid] - mx);
        float sum = e;
        #pragma unroll
        for (int o = 16; o; o >>= 1) sum += __shfl_xor_sync(0xffffffffu, sum, o);
        const int base = (b * 2 + h) * 32 + tid;
        g_wsel[base] = e / sum;
        g_vsel[base] = sh & (VN - 1);
        g_esel[base] = sh >> 18;
    }
}

// ---------------- gather + aggregate -> 3-term split agg (validated) ----------
__global__ __launch_bounds__(256) void agg_kernel(const float* __restrict__ values)
{
    const int b = blockIdx.x, tid = threadIdx.x;
    __shared__ float acc[VE * VD];
    #pragma unroll
    for (int i = 0; i < 4; i++) acc[i * 256 + tid] = 0.f;
    __syncthreads();
    #pragma unroll 4
    for (int j = 0; j < 64; j++) {
        const int base = b * 64 + j;
        float w = g_wsel[base];
        acc[g_esel[base] * 256 + tid] += w * values[(size_t)g_vsel[base] * 256 + tid];
    }
    __syncthreads();
    #pragma unroll
    for (int i = 0; i < 4; i++) {
        __nv_bfloat16 h, m, l; split3(acc[i * 256 + tid], h, m, l);
        const size_t d = (size_t)b * 3072 + i * 256 + tid;
        g_agg3[d] = h; g_agg3[d + 1024] = h; g_agg3[d + 2048] = m;
    }
}

// ---------------- wv[K=1024][N=2048] f32 -> wvt3[N][3K] bf16 {h,m,h} ----------
__global__ __launch_bounds__(256) void conv_wv3(const float* __restrict__ W)
{
    const int K = 1024, N = HDIM;
    __shared__ float t[32][33];
    const int tx = threadIdx.x & 31, ty = threadIdx.x >> 5;
    const int n0 = blockIdx.x * 32, k0 = blockIdx.y * 32;
    #pragma unroll
    for (int r = 0; r < 4; r++)
        t[ty + r * 8][tx] = W[(size_t)(k0 + ty + r * 8) * N + n0 + tx];
    __syncthreads();
    #pragma unroll
    for (int r = 0; r < 4; r++) {
        const int nn = ty + r * 8;
        __nv_bfloat16 h, m, l;
        split3(t[tx][nn], h, m, l);
        __nv_bfloat16* d = g_wvt3 + (size_t)(n0 + nn) * (3 * K) + k0 + tx;
        d[0] = h; d[K] = m; d[2 * K] = h;
    }
}

// ---------------- warp-MMA out-GEMM (validated ≡ fp32 out, R6 vs R11) ---------
// out(BS x HDIM) = agg3(BS x 3072) · wvt3(HDIM x 3072)^T
__global__ __launch_bounds__(256) void mma_out(float* __restrict__ C)
{
    constexpr int N = HDIM, KTOT = 3072;
    __shared__ __align__(128) __nv_bfloat16 sA[2][128 * 32];
    __shared__ __align__(128) __nv_bfloat16 sB[2][128 * 32];

    const int tid = threadIdx.x, wid = tid >> 5, lane = tid & 31;
    const int tn = blockIdx.x, tm = blockIdx.y;
    const int warp_m = wid & 3;
    const int warp_n = wid >> 2;

    const __nv_bfloat16* A = g_agg3 + (size_t)(tm * 128) * KTOT;
    const __nv_bfloat16* B = g_wvt3 + (size_t)(tn * 128) * KTOT;

    const uint32_t sAu = smem_u32(sA);
    const uint32_t sBu = smem_u32(sB);

    const int ldr = tid >> 1;
    const int ldc0 = (tid & 1) * 2;

    float acc[2][8][4];
    #pragma unroll
    for (int i = 0; i < 2; i++)
        #pragma unroll
        for (int j = 0; j < 8; j++)
            #pragma unroll
            for (int q = 0; q < 4; q++) acc[i][j][q] = 0.f;

    constexpr int KT = KTOT / 32;

    auto load_stage = [&](int kt, int s) {
        const __nv_bfloat16* Ag = A + (size_t)ldr * KTOT + kt * 32;
        const __nv_bfloat16* Bg = B + (size_t)ldr * KTOT + kt * 32;
        #pragma unroll
        for (int cc = 0; cc < 2; cc++) {
            const int c = ldc0 + cc;
            const int phys = c ^ (ldr & 3);
            const uint32_t so = (uint32_t)(s * 4096 + ldr * 32 + phys * 8) * 2;
            cpasync16(sAu + so, Ag + c * 8);
            cpasync16(sBu + so, Bg + c * 8);
        }
        CP_COMMIT();
    };

    load_stage(0, 0);
    load_stage(1, 1);

    const int arow = warp_m * 32 + (lane & 7) + ((lane & 8) ? 8 : 0);
    const int acsel = (lane & 16) ? 1 : 0;
    const int brow = warp_n * 64 + (lane & 7) + ((lane & 16) ? 8 : 0);
    const int bcsel = (lane & 8) ? 1 : 0;

    for (int kt = 0; kt < KT; kt++) {
        if (kt == KT - 1) asm volatile("cp.async.wait_group 0;" ::: "memory");
        else              asm volatile("cp.async.wait_group 1;" ::: "memory");
        __syncthreads();
        const int s = kt & 1;

        #pragma unroll
        for (int ks = 0; ks < 2; ks++) {
            uint32_t a[2][4];
            #pragma unroll
            for (int mi = 0; mi < 2; mi++) {
                const int row = arow + mi * 16;
                const int c = ks * 2 + acsel;
                const uint32_t ad = sAu +
                    (uint32_t)(s * 4096 + row * 32 + (c ^ (row & 3)) * 8) * 2;
                LDSM4(a[mi][0], a[mi][1], a[mi][2], a[mi][3], ad);
            }
            uint32_t b[4][4];
            #pragma unroll
            for (int nj = 0; nj < 4; nj++) {
                const int row = brow + nj * 16;
                const int c = ks * 2 + bcsel;
                const uint32_t bd = sBu +
                    (uint32_t)(s * 4096 + row * 32 + (c ^ (row & 3)) * 8) * 2;
                LDSM4(b[nj][0], b[nj][1], b[nj][2], b[nj][3], bd);
            }
            #pragma unroll
            for (int mi = 0; mi < 2; mi++)
                #pragma unroll
                for (int j8 = 0; j8 < 8; j8++) {
                    const int nj = j8 >> 1, p = j8 & 1;
                    MMA16816(acc[mi][j8], a[mi][0], a[mi][1], a[mi][2], a[mi][3],
                             b[nj][p * 2], b[nj][p * 2 + 1]);
                }
        }
        __syncthreads();
        if (kt + 2 < KT) load_stage(kt + 2, s);
    }

    const int g = lane >> 2, tg = lane & 3;
    #pragma unroll
    for (int mi = 0; mi < 2; mi++) {
        const int r0 = tm * 128 + warp_m * 32 + mi * 16 + g;
        #pragma unroll
        for (int j8 = 0; j8 < 8; j8++) {
            const int col = tn * 128 + warp_n * 64 + j8 * 8 + tg * 2;
            *(float2*)&C[(size_t)r0 * N + col] =
                make_float2(acc[mi][j8][0], acc[mi][j8][1]);
            *(float2*)&C[(size_t)(r0 + 8) * N + col] =
                make_float2(acc[mi][j8][2], acc[mi][j8][3]);
        }
    }
}

// ---------------- launch (kernel launches only) ----------------
extern "C" void kernel_launch(void* const* d_in, const int* in_sizes, int n_in,
                              void* d_out, int out_size)
{
    const float* hidden = (const float*)d_in[0];
    const float* wq     = (const float*)d_in[1];
    const float* qnw    = (const float*)d_in[2];
    const float* knw    = (const float*)d_in[3];
    const float* keys   = (const float*)d_in[4];
    const float* core   = (const float*)d_in[5];
    const float* tu     = (const float*)d_in[6];
    const float* tv     = (const float*)d_in[7];
    const float* values = (const float*)d_in[8];
    const float* wvm    = (const float*)d_in[9];
    const int*   shuf   = (const int*)d_in[10];
    float* out = (float*)d_out;

    // pre-selection: bit-identical to the R2 run that passed
    sgemm_kernel<TAGF_EXT, TAGF_EXT, TAGF_QRAW>
        <<<dim3(512/128, BS/128), 256>>>(hidden, wq, nullptr, BS, 512, HDIM);
    qln_kernel<<<BS * 2, 256>>>(qnw);
    keysn_kernel<<<2 * 2 * KN, 256>>>(keys, knw);
    sgemm_kernel<TAGF_QN0, TAGF_KB0, TAGF_SR0>
        <<<dim3(SCOL/128, BS/128), 256>>>(nullptr, nullptr, nullptr, BS, SCOL, KD);
    sgemm_kernel<TAGF_QN1, TAGF_KB1, TAGF_SR1>
        <<<dim3(SCOL/128, BS/128), 256>>>(nullptr, nullptr, nullptr, BS, SCOL, KD);

    // post-selection: fast validated path
    conv_wv3<<<dim3(HDIM/32, 1024/32), 256>>>(wvm);
    select_kernel<<<dim3(BS, 2), 256>>>(core, tu, tv, shuf);
    agg_kernel<<<BS, 256>>>(values);
    mma_out<<<dim3(HDIM/128, BS/128), 256>>>(out);
}